// round 14
// baseline (speedup 1.0000x reference)
#include <cuda_runtime.h>
#include <cstdint>

// RegL1Loss: out[b] = sum_{p,d} valid * |preds[b, idx] - val| / num_people[b]
// B=32, P=64, D=34, L=1048576. gts packed as [...,3] = (val, idx_as_float, flag).
//
// Single-node spread design: 4 CTAs per batch (grid=128) cuts the per-SM
// L1tex wavefront load on the random gathers 4x (544 lines/SM vs 2176).
// Combine tail is fully self-resetting so the graph has exactly ONE node:
//   each CTA: atomicAdd partials -> threadfence -> atomicInc(ticket, 3)
//   (atomicInc wraps 3 -> 0, so the ticket resets itself);
//   winner (old==3): atomicExch(scratch, 0) reads the full sum AND re-zeroes
//   it for the next replay in one L2 atomic. No memset node, no fences beyond
//   the one release, no volatile chains.

#define B 32
#define P 64
#define D 34
#define PD (P * D)          // 2176
#define L 1048576
#define SPLITS 4
#define EPC (PD / SPLITS)   // 544 elements per CTA = 16 persons (person-aligned)
#define PPC (EPC / D)       // 16
#define LOADERS (EPC / 4)   // 136 loader threads, 4 elements each
#define TPC 160             // 5 warps
#define NW (TPC / 32)

__device__ float    g_sum[B];     // zero at load; atomicExch re-zeroes each run
__device__ int      g_cnt[B];
__device__ unsigned g_ticket[B];  // atomicInc(.,3) self-wraps to 0

__global__ __launch_bounds__(TPC) void regl1_kernel(
    const float* __restrict__ preds,
    const float* __restrict__ gts,
    float* __restrict__ out)
{
    const int cta   = blockIdx.x;
    const int b     = cta >> 2;
    const int split = cta & 3;
    const int tid   = threadIdx.x;

    __shared__ int   pv[PPC];
    __shared__ float wsum[NW];

    if (tid < PPC) pv[tid] = 0;
    __syncthreads();

    float acc = 0.0f;
    if (tid < LOADERS) {
        // 12 consecutive floats per thread = 3 float4 loads (48B/thread).
        const float4* __restrict__ g4 =
            (const float4*)(gts + ((size_t)b * PD + split * EPC) * 3) +
            (size_t)tid * 3;
        const float* __restrict__ pr = preds + (size_t)b * L;

        float4 a0 = g4[0];
        float4 a1 = g4[1];
        float4 a2 = g4[2];

        float vals[4] = { a0.x, a0.w, a1.z, a2.y };
        float fidx[4] = { a0.y, a1.x, a1.w, a2.z };
        float flag[4] = { a0.z, a1.y, a2.x, a2.w };

        bool  v[4];
        float gat[4];
        #pragma unroll
        for (int i = 0; i < 4; i++) {
            v[i]   = flag[i] > 0.0f;
            gat[i] = v[i] ? __ldg(pr + (int)fidx[i]) : 0.0f;  // independent gathers
        }

        const int e0 = tid * 4;
        #pragma unroll
        for (int i = 0; i < 4; i++) {
            if (v[i]) {
                acc += fabsf(gat[i] - vals[i]);
                pv[(e0 + i) / D] = 1;   // benign race: all writers store 1
            }
        }
    }

    // intra-CTA reduce
    #pragma unroll
    for (int off = 16; off > 0; off >>= 1)
        acc += __shfl_xor_sync(0xFFFFFFFFu, acc, off);

    const int wid = tid >> 5;
    const int lid = tid & 31;
    if (lid == 0) wsum[wid] = acc;
    __syncthreads();

    if (tid == 0) {
        float total = 0.0f;
        #pragma unroll
        for (int w = 0; w < NW; w++) total += wsum[w];
        int cnt = 0;
        #pragma unroll
        for (int p = 0; p < PPC; p++) cnt += pv[p];

        atomicAdd(&g_sum[b], total);
        atomicAdd(&g_cnt[b], cnt);
        __threadfence();                              // release data atomics
        unsigned t = atomicInc(&g_ticket[b], SPLITS - 1);  // wraps 3 -> 0
        if (t == SPLITS - 1) {
            __threadfence();                          // order after ticket obs
            float s = atomicExch(&g_sum[b], 0.0f);    // read + reset in one op
            int   c = atomicExch(&g_cnt[b], 0);
            out[b] = s / (float)c;
        }
    }
}

extern "C" void kernel_launch(void* const* d_in, const int* in_sizes, int n_in,
                              void* d_out, int out_size)
{
    const float* preds = (const float*)d_in[0];
    const float* gts   = (const float*)d_in[1];
    float* out = (float*)d_out;
    regl1_kernel<<<B * SPLITS, TPC>>>(preds, gts, out);
}

// round 17
// speedup vs baseline: 1.1783x; 1.1783x over previous
#include <cuda_runtime.h>

// RegL1Loss: out[b] = sum_{p,d} valid * |preds[b, idx] - val| / num_people[b]
// B=32, P=64, D=34, L=1048576. gts packed as [...,3] = (val, idx_as_float, flag).
//
// Locked structure (empirically best on this harness): grid=32 (one CTA per
// batch), single pass, zero cross-CTA coordination. 256 threads over 544
// float4-groups: every thread owns group t and t+256 unconditionally, plus
// group t+512 if t<32. All vector loads and all gathers are front-batched
// (no loop), giving max MLP into the per-SM L1tex wavefront queue, which is
// the warm-path bottleneck (~2176 random gather lines per SM).

#define B 32
#define P 64
#define D 34
#define PD (P * D)          // 2176
#define L 1048576
#define NT 256
#define NGROUP (PD / 4)     // 544 groups of 4 elements (3 float4s each)

__global__ __launch_bounds__(NT) void regl1_kernel(
    const float* __restrict__ preds,
    const float* __restrict__ gts,
    float* __restrict__ out)
{
    const int b   = blockIdx.x;
    const int tid = threadIdx.x;

    __shared__ int   pv[P];
    __shared__ float wsum[NT / 32];

    if (tid < P) pv[tid] = 0;
    __syncthreads();

    const float4* __restrict__ gbase = (const float4*)(gts + (size_t)b * PD * 3);
    const float* __restrict__ pr = preds + (size_t)b * L;

    const bool has3 = (tid < NGROUP - 2 * NT);   // tid < 32
    const int  g0 = tid, g1 = tid + NT, g2 = tid + 2 * NT;

    // ---- front-batched vector loads of gts (all independent) ----
    float4 r0a = gbase[(size_t)g0 * 3 + 0];
    float4 r0b = gbase[(size_t)g0 * 3 + 1];
    float4 r0c = gbase[(size_t)g0 * 3 + 2];
    float4 r1a = gbase[(size_t)g1 * 3 + 0];
    float4 r1b = gbase[(size_t)g1 * 3 + 1];
    float4 r1c = gbase[(size_t)g1 * 3 + 2];
    float4 r2a, r2b, r2c;
    if (has3) {
        r2a = gbase[(size_t)g2 * 3 + 0];
        r2b = gbase[(size_t)g2 * 3 + 1];
        r2c = gbase[(size_t)g2 * 3 + 2];
    } else {
        r2a = r2b = r2c = make_float4(0.f, 0.f, -1.f, -1.f); // flags<=0 -> inert
    }

    // unpack: group layout (val,idx,flag)x4 across 3 float4s
    float vals[12] = { r0a.x, r0a.w, r0b.z, r0c.y,
                       r1a.x, r1a.w, r1b.z, r1c.y,
                       r2a.x, r2a.w, r2b.z, r2c.y };
    float fidx[12] = { r0a.y, r0b.x, r0b.w, r0c.z,
                       r1a.y, r1b.x, r1b.w, r1c.z,
                       r2a.y, r2b.x, r2b.w, r2c.z };
    float flag[12] = { r0a.z, r0b.y, r0c.x, r0c.w,
                       r1a.z, r1b.y, r1c.x, r1c.w,
                       r2a.z, r2b.y, r2c.x, r2c.w };

    // ---- front-batched independent predicated gathers ----
    bool  v[12];
    float gat[12];
    #pragma unroll
    for (int i = 0; i < 12; i++) {
        v[i]   = flag[i] > 0.0f;
        gat[i] = v[i] ? __ldg(pr + (int)fidx[i]) : 0.0f;
    }

    // ---- accumulate + person-valid flags (benign race: all store 1) ----
    const int e[3] = { g0 * 4, g1 * 4, g2 * 4 };
    float acc = 0.0f;
    #pragma unroll
    for (int i = 0; i < 12; i++) {
        if (v[i]) {
            acc += fabsf(gat[i] - vals[i]);
            pv[(e[i >> 2] + (i & 3)) / D] = 1;
        }
    }

    // ---- reduce ----
    #pragma unroll
    for (int off = 16; off > 0; off >>= 1)
        acc += __shfl_xor_sync(0xFFFFFFFFu, acc, off);

    const int wid = tid >> 5;
    const int lid = tid & 31;
    if (lid == 0) wsum[wid] = acc;
    __syncthreads();

    if (wid == 0) {
        float total = (lid < NT / 32) ? wsum[lid] : 0.0f;
        #pragma unroll
        for (int off = 16; off > 0; off >>= 1)
            total += __shfl_xor_sync(0xFFFFFFFFu, total, off);

        int cnt = pv[lid] + pv[lid + 32];
        #pragma unroll
        for (int off = 16; off > 0; off >>= 1)
            cnt += __shfl_xor_sync(0xFFFFFFFFu, cnt, off);

        if (lid == 0)
            out[b] = total / (float)cnt;
    }
}

extern "C" void kernel_launch(void* const* d_in, const int* in_sizes, int n_in,
                              void* d_out, int out_size)
{
    const float* preds = (const float*)d_in[0];
    const float* gts   = (const float*)d_in[1];
    float* out = (float*)d_out;
    regl1_kernel<<<B, NT>>>(preds, gts, out);
}